// round 1
// baseline (speedup 1.0000x reference)
#include <cuda_runtime.h>
#include <math_constants.h>
#include <cstddef>

#define DIM 1024
#define NSEG 1024
#define SEQ 2048

// ---------------- static scratch (no allocations allowed) ----------------
__device__ float g_raw[NSEG * 2 * DIM];   // pooled max||mean  [1024, 2048]
__device__ float g_x0 [NSEG * DIM];       // pooler tanh out
__device__ float g_y  [NSEG * DIM];       // GEMM scratch (pre-BN)
__device__ float g_p  [NSEG * DIM];       // pool_lb output (tower input)
__device__ float g_a  [NSEG * DIM];       // tower ping
__device__ float g_b  [NSEG * DIM];       // tower pong

// ---------------- ragged segment max/mean pooling ----------------
// segment s = b*16 + j ; tokens p in [1+sum(parts[b][0..j-1]), +parts[b][j])
__global__ void pool_kernel(const float* __restrict__ h,
                            const int* __restrict__ turns,
                            const int* __restrict__ parts,
                            float* __restrict__ raw) {
    int s = blockIdx.x;
    int b = s >> 4;
    int j = s & 15;
    int start = 1;
    #pragma unroll
    for (int t = 0; t < 16; ++t)
        if (t < j) start += parts[b * 16 + t];
    int count = parts[b * 16 + j];
    bool valid = (j < turns[b]);
    const float* base = h + ((size_t)b * SEQ + start) * DIM;

    for (int d = threadIdx.x; d < DIM; d += blockDim.x) {
        float mx = -CUDART_INF_F;
        float sm = 0.0f;
        if (valid) {
            for (int p = 0; p < count; ++p) {
                float v = base[(size_t)p * DIM + d];
                mx = fmaxf(mx, v);
                sm += v;
            }
            sm /= (float)count;
        } else {
            sm = CUDART_NAN_F;
        }
        raw[(size_t)s * (2 * DIM) + d]        = mx;
        raw[(size_t)s * (2 * DIM) + DIM + d]  = sm;
    }
}

// ---------------- fp32 tiled GEMM: Y[M,N] = A[M,K] @ W[K,N] (+bias)(+tanh) ----------------
// BM=128, BN=64, BK=8, 128 threads, 8x8 per thread. N fixed = 1024.
template <bool TANH>
__global__ __launch_bounds__(128)
void gemm_kernel(const float* __restrict__ A, const float* __restrict__ W,
                 const float* __restrict__ bias, float* __restrict__ Y,
                 int K, int lda) {
    const int N = 1024;
    __shared__ float As[8][128];
    __shared__ float Bs[8][64];

    int tid = threadIdx.x;
    int tx = tid & 7;    // col group (8 groups of 8 cols)
    int ty = tid >> 3;   // row group (16 groups of 8 rows)
    int bm = blockIdx.y * 128;
    int bn = blockIdx.x * 64;

    float acc[8][8];
    #pragma unroll
    for (int i = 0; i < 8; ++i)
        #pragma unroll
        for (int jj = 0; jj < 8; ++jj) acc[i][jj] = 0.0f;

    const float* Aload = A + (size_t)(bm + tid) * lda;
    int brow = tid >> 4;          // 0..7
    int bcol = (tid & 15) * 4;    // 0..60

    for (int k0 = 0; k0 < K; k0 += 8) {
        float4 a0 = *(const float4*)(Aload + k0);
        float4 a1 = *(const float4*)(Aload + k0 + 4);
        As[0][tid] = a0.x; As[1][tid] = a0.y; As[2][tid] = a0.z; As[3][tid] = a0.w;
        As[4][tid] = a1.x; As[5][tid] = a1.y; As[6][tid] = a1.z; As[7][tid] = a1.w;
        float4 bv = *(const float4*)(W + (size_t)(k0 + brow) * N + bn + bcol);
        *(float4*)&Bs[brow][bcol] = bv;
        __syncthreads();

        #pragma unroll
        for (int kk = 0; kk < 8; ++kk) {
            float4 af0 = *(const float4*)&As[kk][ty * 8];
            float4 af1 = *(const float4*)&As[kk][ty * 8 + 4];
            float4 bf0 = *(const float4*)&Bs[kk][tx * 8];
            float4 bf1 = *(const float4*)&Bs[kk][tx * 8 + 4];
            float a[8] = {af0.x, af0.y, af0.z, af0.w, af1.x, af1.y, af1.z, af1.w};
            float b[8] = {bf0.x, bf0.y, bf0.z, bf0.w, bf1.x, bf1.y, bf1.z, bf1.w};
            #pragma unroll
            for (int i = 0; i < 8; ++i)
                #pragma unroll
                for (int jj = 0; jj < 8; ++jj)
                    acc[i][jj] += a[i] * b[jj];
        }
        __syncthreads();
    }

    #pragma unroll
    for (int i = 0; i < 8; ++i) {
        int row = bm + ty * 8 + i;
        #pragma unroll
        for (int jq = 0; jq < 2; ++jq) {
            int col = bn + tx * 8 + jq * 4;
            float4 v;
            v.x = acc[i][jq * 4 + 0];
            v.y = acc[i][jq * 4 + 1];
            v.z = acc[i][jq * 4 + 2];
            v.w = acc[i][jq * 4 + 3];
            if (bias) {
                v.x += bias[col + 0]; v.y += bias[col + 1];
                v.z += bias[col + 2]; v.w += bias[col + 3];
            }
            if (TANH) {
                v.x = tanhf(v.x); v.y = tanhf(v.y);
                v.z = tanhf(v.z); v.w = tanhf(v.w);
            }
            *(float4*)&Y[(size_t)row * N + col] = v;
        }
    }
}

// ---------------- BatchNorm1d (training stats) + tanh ----------------
// grid: 32 blocks x 32 cols each, 256 threads (32 cols x 8 row-slices)
__global__ void bn_tanh_kernel(const float* __restrict__ Y,
                               const float* __restrict__ g,
                               const float* __restrict__ beta,
                               float* __restrict__ out) {
    __shared__ float sh_s[8][32];
    __shared__ float sh_q[8][32];
    __shared__ float sh_scale[32];
    __shared__ float sh_shift[32];

    int lane = threadIdx.x & 31;
    int r0   = threadIdx.x >> 5;   // 0..7
    int c    = blockIdx.x * 32 + lane;

    float s = 0.0f, q = 0.0f;
    for (int r = r0; r < 1024; r += 8) {
        float v = Y[(size_t)r * 1024 + c];
        s += v; q += v * v;
    }
    sh_s[r0][lane] = s;
    sh_q[r0][lane] = q;
    __syncthreads();

    if (r0 == 0) {
        float ts = 0.0f, tq = 0.0f;
        #pragma unroll
        for (int i = 0; i < 8; ++i) { ts += sh_s[i][lane]; tq += sh_q[i][lane]; }
        float mean = ts * (1.0f / 1024.0f);
        float var  = fmaxf(tq * (1.0f / 1024.0f) - mean * mean, 0.0f);
        float rs   = rsqrtf(var + 1e-5f);
        float scale = g[c] * rs;
        sh_scale[lane] = scale;
        sh_shift[lane] = beta[c] - mean * scale;
    }
    __syncthreads();

    float scale = sh_scale[lane];
    float shift = sh_shift[lane];
    for (int r = r0; r < 1024; r += 8)
        out[(size_t)r * 1024 + c] = tanhf(Y[(size_t)r * 1024 + c] * scale + shift);
}

// ---------------- small head GEMM: out[M, nout] = X[M,1024] @ Wf + bf ----------------
__global__ void final_kernel(const float* __restrict__ X,
                             const float* __restrict__ Wf,
                             const float* __restrict__ bf,
                             float* __restrict__ out, int nout) {
    __shared__ float sh[1024];
    int m = blockIdx.x;
    for (int k = threadIdx.x; k < 1024; k += blockDim.x)
        sh[k] = X[(size_t)m * 1024 + k];
    __syncthreads();
    for (int n = threadIdx.x; n < nout; n += blockDim.x) {
        float acc = bf[n];
        #pragma unroll 4
        for (int k = 0; k < 1024; ++k)
            acc += sh[k] * Wf[(size_t)k * nout + n];
        out[(size_t)m * nout + n] = acc;
    }
}

// ---------------- launch ----------------
extern "C" void kernel_launch(void* const* d_in, const int* in_sizes, int n_in,
                              void* d_out, int out_size) {
    const float* h        = (const float*)d_in[0];
    const int*   turns    = (const int*)  d_in[1];
    const int*   parts    = (const int*)  d_in[2];
    const float* pooler_W = (const float*)d_in[3];
    const float* pooler_b = (const float*)d_in[4];
    const float* pool_W   = (const float*)d_in[5];
    // d_in[6] = pool_b: exactly cancelled by BatchNorm mean subtraction
    const float* pool_g   = (const float*)d_in[7];
    const float* pool_be  = (const float*)d_in[8];
    float* out = (float*)d_out;

    float *raw, *x0, *y, *p, *a, *b;
    cudaGetSymbolAddress((void**)&raw, g_raw);
    cudaGetSymbolAddress((void**)&x0,  g_x0);
    cudaGetSymbolAddress((void**)&y,   g_y);
    cudaGetSymbolAddress((void**)&p,   g_p);
    cudaGetSymbolAddress((void**)&a,   g_a);
    cudaGetSymbolAddress((void**)&b,   g_b);

    // 1) ragged pooling -> [1024, 2048]
    pool_kernel<<<NSEG, 256>>>(h, turns, parts, raw);

    // 2) pooler: tanh(raw @ pooler_W + pooler_b), K=2048
    gemm_kernel<true><<<dim3(16, 8), 128>>>(raw, pooler_W, pooler_b, x0, 2048, 2048);

    // 3) pool Linear_Block (bias cancels under BN)
    gemm_kernel<false><<<dim3(16, 8), 128>>>(x0, pool_W, nullptr, y, 1024, 1024);
    bn_tanh_kernel<<<32, 256>>>(y, pool_g, pool_be, p);

    // 4) three towers (emo: nout=7, act: 5, int: 102)
    const int   nouts[3] = {7, 5, 102};
    const int   offs [3] = {0, 7 * NSEG, 12 * NSEG};
    for (int t = 0; t < 3; ++t) {
        const float* Ws    = (const float*)d_in[9  + 6 * t];
        // d_in[10+6t] = bs: cancelled by BN
        const float* gs    = (const float*)d_in[11 + 6 * t];
        const float* betas = (const float*)d_in[12 + 6 * t];
        const float* Wf    = (const float*)d_in[13 + 6 * t];
        const float* bf    = (const float*)d_in[14 + 6 * t];

        const float* x = p;
        float* pp[2] = {a, b};
        for (int k = 0; k < 4; ++k) {
            gemm_kernel<false><<<dim3(16, 8), 128>>>(x, Ws + (size_t)k * DIM * DIM,
                                                     nullptr, y, 1024, 1024);
            float* nx = pp[k & 1];
            bn_tanh_kernel<<<32, 256>>>(y, gs + k * DIM, betas + k * DIM, nx);
            x = nx;
        }
        final_kernel<<<NSEG, 128>>>(x, Wf, bf, out + offs[t], nouts[t]);
    }
}

// round 2
// speedup vs baseline: 1.6611x; 1.6611x over previous
#include <cuda_runtime.h>
#include <math_constants.h>
#include <cstddef>

#define DIM 1024
#define NSEG 1024
#define SEQ 2048

// ---------------- static scratch (no allocations allowed) ----------------
__device__ __align__(16) float g_raw[NSEG * 2 * DIM];   // pooled max||mean  [1024, 2048]
__device__ __align__(16) float g_x0 [NSEG * DIM];       // pooler tanh out
__device__ __align__(16) float g_y  [NSEG * DIM];       // GEMM scratch (pre-BN)
__device__ __align__(16) float g_p  [NSEG * DIM];       // pool_lb output (tower input)
__device__ __align__(16) float g_a  [NSEG * DIM];       // tower ping
__device__ __align__(16) float g_b  [NSEG * DIM];       // tower pong
__device__ __align__(16) float g_psum[8 * DIM];         // per-M-block column sums
__device__ __align__(16) float g_psq [8 * DIM];         // per-M-block column sumsq
__device__ __align__(16) float g_scale[DIM];
__device__ __align__(16) float g_shift[DIM];

// ---------------- ragged segment max/mean pooling ----------------
// segment s = b*16 + j ; tokens p in [1+sum(parts[b][0..j-1]), +parts[b][j])
__global__ __launch_bounds__(256)
void pool_kernel(const float* __restrict__ h,
                 const int* __restrict__ turns,
                 const int* __restrict__ parts,
                 float* __restrict__ raw) {
    int s = blockIdx.x;
    int b = s >> 4;
    int j = s & 15;
    int start = 1;
    #pragma unroll
    for (int t = 0; t < 16; ++t)
        if (t < j) start += parts[b * 16 + t];
    int count = parts[b * 16 + j];
    bool valid = (j < turns[b]);
    const float4* base = (const float4*)(h + ((size_t)b * SEQ + start) * DIM);
    int d4 = threadIdx.x;  // 256 threads * 4 floats = 1024 dims

    float4 mx = make_float4(-CUDART_INF_F, -CUDART_INF_F, -CUDART_INF_F, -CUDART_INF_F);
    float4 sm = make_float4(0.f, 0.f, 0.f, 0.f);
    if (valid) {
        int p = 0;
        for (; p + 1 < count; p += 2) {
            float4 v0 = base[(size_t)p * 256 + d4];
            float4 v1 = base[(size_t)(p + 1) * 256 + d4];
            mx.x = fmaxf(mx.x, fmaxf(v0.x, v1.x));
            mx.y = fmaxf(mx.y, fmaxf(v0.y, v1.y));
            mx.z = fmaxf(mx.z, fmaxf(v0.z, v1.z));
            mx.w = fmaxf(mx.w, fmaxf(v0.w, v1.w));
            sm.x += v0.x + v1.x; sm.y += v0.y + v1.y;
            sm.z += v0.z + v1.z; sm.w += v0.w + v1.w;
        }
        if (p < count) {
            float4 v0 = base[(size_t)p * 256 + d4];
            mx.x = fmaxf(mx.x, v0.x); mx.y = fmaxf(mx.y, v0.y);
            mx.z = fmaxf(mx.z, v0.z); mx.w = fmaxf(mx.w, v0.w);
            sm.x += v0.x; sm.y += v0.y; sm.z += v0.z; sm.w += v0.w;
        }
        float inv = 1.0f / (float)count;
        sm.x *= inv; sm.y *= inv; sm.z *= inv; sm.w *= inv;
    } else {
        sm = make_float4(CUDART_NAN_F, CUDART_NAN_F, CUDART_NAN_F, CUDART_NAN_F);
    }
    float4* outr = (float4*)(raw + (size_t)s * (2 * DIM));
    outr[d4]       = mx;
    outr[256 + d4] = sm;
}

// ---------------- fp32 double-buffered GEMM ----------------
// Y[M,1024] = A[M,K] @ W[K,1024] (+bias,+tanh | +BN column stats)
// BM=128, BN=64, BK=16, 256 threads, 8x4 per thread.
template <bool TANH, bool STATS>
__global__ __launch_bounds__(256)
void gemm_kernel(const float* __restrict__ A, const float* __restrict__ W,
                 const float* __restrict__ bias, float* __restrict__ Y,
                 float* __restrict__ psum, float* __restrict__ psq,
                 int K, int lda) {
    const int N = 1024;
    __shared__ float As[2][16][128];
    __shared__ float Bs[2][16][64];
    __shared__ float red[16][64];

    int tid = threadIdx.x;
    int tx = tid & 15;       // N groups (16 x 4 cols)
    int ty = tid >> 4;       // M groups (16 x 8 rows)
    int bm = blockIdx.y * 128;
    int bn = blockIdx.x * 64;

    // A-tile load mapping: two float4 per thread
    int ar0 = tid >> 2;            // rows 0..63
    int ak  = (tid & 3) * 4;       // k offset 0,4,8,12
    // B-tile load mapping: one float4 per thread
    int brow = tid >> 4;           // 0..15
    int bcol = (tid & 15) * 4;     // 0..60

    const float* Ap0 = A + (size_t)(bm + ar0) * lda + ak;
    const float* Ap1 = A + (size_t)(bm + ar0 + 64) * lda + ak;
    const float* Wp  = W + (size_t)brow * N + bn + bcol;

    float acc[8][4];
    #pragma unroll
    for (int i = 0; i < 8; ++i)
        #pragma unroll
        for (int jj = 0; jj < 4; ++jj) acc[i][jj] = 0.0f;

    // ---- initial tile ----
    {
        float4 a0 = *(const float4*)(Ap0);
        float4 a1 = *(const float4*)(Ap1);
        float4 bv = *(const float4*)(Wp);
        As[0][ak + 0][ar0] = a0.x; As[0][ak + 1][ar0] = a0.y;
        As[0][ak + 2][ar0] = a0.z; As[0][ak + 3][ar0] = a0.w;
        As[0][ak + 0][ar0 + 64] = a1.x; As[0][ak + 1][ar0 + 64] = a1.y;
        As[0][ak + 2][ar0 + 64] = a1.z; As[0][ak + 3][ar0 + 64] = a1.w;
        *(float4*)&Bs[0][brow][bcol] = bv;
    }
    __syncthreads();

    int buf = 0;
    for (int k0 = 16; k0 < K; k0 += 16) {
        // global prefetch
        float4 a0 = *(const float4*)(Ap0 + k0);
        float4 a1 = *(const float4*)(Ap1 + k0);
        float4 bv = *(const float4*)(Wp + (size_t)k0 * N);

        #pragma unroll
        for (int kk = 0; kk < 16; ++kk) {
            float4 af0 = *(const float4*)&As[buf][kk][ty * 8];
            float4 af1 = *(const float4*)&As[buf][kk][ty * 8 + 4];
            float4 bf  = *(const float4*)&Bs[buf][kk][tx * 4];
            float a[8] = {af0.x, af0.y, af0.z, af0.w, af1.x, af1.y, af1.z, af1.w};
            float b[4] = {bf.x, bf.y, bf.z, bf.w};
            #pragma unroll
            for (int i = 0; i < 8; ++i)
                #pragma unroll
                for (int jj = 0; jj < 4; ++jj)
                    acc[i][jj] += a[i] * b[jj];
        }

        int nb = buf ^ 1;
        As[nb][ak + 0][ar0] = a0.x; As[nb][ak + 1][ar0] = a0.y;
        As[nb][ak + 2][ar0] = a0.z; As[nb][ak + 3][ar0] = a0.w;
        As[nb][ak + 0][ar0 + 64] = a1.x; As[nb][ak + 1][ar0 + 64] = a1.y;
        As[nb][ak + 2][ar0 + 64] = a1.z; As[nb][ak + 3][ar0 + 64] = a1.w;
        *(float4*)&Bs[nb][brow][bcol] = bv;
        __syncthreads();
        buf = nb;
    }
    // last tile compute
    #pragma unroll
    for (int kk = 0; kk < 16; ++kk) {
        float4 af0 = *(const float4*)&As[buf][kk][ty * 8];
        float4 af1 = *(const float4*)&As[buf][kk][ty * 8 + 4];
        float4 bf  = *(const float4*)&Bs[buf][kk][tx * 4];
        float a[8] = {af0.x, af0.y, af0.z, af0.w, af1.x, af1.y, af1.z, af1.w};
        float b[4] = {bf.x, bf.y, bf.z, bf.w};
        #pragma unroll
        for (int i = 0; i < 8; ++i)
            #pragma unroll
            for (int jj = 0; jj < 4; ++jj)
                acc[i][jj] += a[i] * b[jj];
    }

    // ---- epilogue ----
    #pragma unroll
    for (int i = 0; i < 8; ++i) {
        int row = bm + ty * 8 + i;
        int col = bn + tx * 4;
        float4 v = make_float4(acc[i][0], acc[i][1], acc[i][2], acc[i][3]);
        if (TANH) {
            v.x = tanhf(v.x + bias[col + 0]);
            v.y = tanhf(v.y + bias[col + 1]);
            v.z = tanhf(v.z + bias[col + 2]);
            v.w = tanhf(v.w + bias[col + 3]);
        }
        *(float4*)&Y[(size_t)row * N + col] = v;
    }

    if (STATS) {
        // column partial sums over this block's 128 rows (deterministic, no atomics)
        float s[4], q[4];
        #pragma unroll
        for (int jj = 0; jj < 4; ++jj) { s[jj] = 0.f; q[jj] = 0.f; }
        #pragma unroll
        for (int i = 0; i < 8; ++i)
            #pragma unroll
            for (int jj = 0; jj < 4; ++jj) {
                float v = acc[i][jj];
                s[jj] += v; q[jj] += v * v;
            }
        __syncthreads();
        #pragma unroll
        for (int jj = 0; jj < 4; ++jj) red[ty][tx * 4 + jj] = s[jj];
        __syncthreads();
        if (tid < 64) {
            float t = 0.f;
            #pragma unroll
            for (int g = 0; g < 16; ++g) t += red[g][tid];
            psum[(size_t)blockIdx.y * 1024 + bn + tid] = t;
        }
        __syncthreads();
        #pragma unroll
        for (int jj = 0; jj < 4; ++jj) red[ty][tx * 4 + jj] = q[jj];
        __syncthreads();
        if (tid < 64) {
            float t = 0.f;
            #pragma unroll
            for (int g = 0; g < 16; ++g) t += red[g][tid];
            psq[(size_t)blockIdx.y * 1024 + bn + tid] = t;
        }
    }
}

// ---------------- BN scale/shift from partials ----------------
__global__ void bn_scale_kernel(const float* __restrict__ psum,
                                const float* __restrict__ psq,
                                const float* __restrict__ g,
                                const float* __restrict__ beta,
                                float* __restrict__ scale,
                                float* __restrict__ shift) {
    int c = blockIdx.x * 256 + threadIdx.x;
    float s = 0.f, q = 0.f;
    #pragma unroll
    for (int i = 0; i < 8; ++i) {
        s += psum[i * 1024 + c];
        q += psq[i * 1024 + c];
    }
    float mean = s * (1.0f / 1024.0f);
    float var  = fmaxf(q * (1.0f / 1024.0f) - mean * mean, 0.0f);
    float rs   = rsqrtf(var + 1e-5f);
    float sc   = g[c] * rs;
    scale[c] = sc;
    shift[c] = beta[c] - mean * sc;
}

// ---------------- elementwise BN apply + tanh (float4) ----------------
__global__ __launch_bounds__(256)
void bn_apply_kernel(const float* __restrict__ Y,
                     const float* __restrict__ scale,
                     const float* __restrict__ shift,
                     float* __restrict__ out) {
    int i = blockIdx.x * 256 + threadIdx.x;   // float4 index, grid covers 2 passes
    const float4* Y4 = (const float4*)Y;
    const float4* sc4 = (const float4*)scale;
    const float4* sh4 = (const float4*)shift;
    float4* o4 = (float4*)out;
    #pragma unroll
    for (int pass = 0; pass < 2; ++pass) {
        int idx = i + pass * 131072;           // 262144 float4 total
        float4 v = Y4[idx];
        int c = idx & 255;
        float4 sc = sc4[c], sh = sh4[c];
        v.x = tanhf(v.x * sc.x + sh.x);
        v.y = tanhf(v.y * sc.y + sh.y);
        v.z = tanhf(v.z * sc.z + sh.z);
        v.w = tanhf(v.w * sc.w + sh.w);
        o4[idx] = v;
    }
}

// ---------------- small head GEMM: out[1024, nout] = X @ Wf + bf ----------------
// 8 rows per block, X tile in smem, Wf streamed (L2-resident).
__global__ __launch_bounds__(128)
void final_kernel(const float* __restrict__ X,
                  const float* __restrict__ Wf,
                  const float* __restrict__ bf,
                  float* __restrict__ out, int nout) {
    __shared__ float sh[8][1024];
    int r0 = blockIdx.x * 8;
    const float4* Xs = (const float4*)(X + (size_t)r0 * 1024);
    #pragma unroll
    for (int q = 0; q < 16; ++q) {
        int i = threadIdx.x + q * 128;   // float4 idx over 8*256
        int row = i >> 8, col4 = (i & 255);
        *(float4*)&sh[row][col4 * 4] = Xs[(size_t)row * 256 + col4];
    }
    __syncthreads();
    for (int n = threadIdx.x; n < nout; n += 128) {
        float acc[8];
        float bv = bf[n];
        #pragma unroll
        for (int r = 0; r < 8; ++r) acc[r] = bv;
        #pragma unroll 8
        for (int k = 0; k < 1024; ++k) {
            float w = Wf[(size_t)k * nout + n];
            #pragma unroll
            for (int r = 0; r < 8; ++r) acc[r] += sh[r][k] * w;
        }
        #pragma unroll
        for (int r = 0; r < 8; ++r)
            out[(size_t)(r0 + r) * nout + n] = acc[r];
    }
}

// ---------------- launch ----------------
extern "C" void kernel_launch(void* const* d_in, const int* in_sizes, int n_in,
                              void* d_out, int out_size) {
    const float* h        = (const float*)d_in[0];
    const int*   turns    = (const int*)  d_in[1];
    const int*   parts    = (const int*)  d_in[2];
    const float* pooler_W = (const float*)d_in[3];
    const float* pooler_b = (const float*)d_in[4];
    const float* pool_W   = (const float*)d_in[5];
    // d_in[6] = pool_b: exactly cancelled by BatchNorm mean subtraction
    const float* pool_g   = (const float*)d_in[7];
    const float* pool_be  = (const float*)d_in[8];
    float* out = (float*)d_out;

    float *raw, *x0, *y, *p, *a, *b, *psum, *psq, *scale, *shift;
    cudaGetSymbolAddress((void**)&raw,  g_raw);
    cudaGetSymbolAddress((void**)&x0,   g_x0);
    cudaGetSymbolAddress((void**)&y,    g_y);
    cudaGetSymbolAddress((void**)&p,    g_p);
    cudaGetSymbolAddress((void**)&a,    g_a);
    cudaGetSymbolAddress((void**)&b,    g_b);
    cudaGetSymbolAddress((void**)&psum, g_psum);
    cudaGetSymbolAddress((void**)&psq,  g_psq);
    cudaGetSymbolAddress((void**)&scale,g_scale);
    cudaGetSymbolAddress((void**)&shift,g_shift);

    dim3 gg(16, 8);

    // 1) ragged pooling -> [1024, 2048]
    pool_kernel<<<NSEG, 256>>>(h, turns, parts, raw);

    // 2) pooler: tanh(raw @ pooler_W + pooler_b), K=2048
    gemm_kernel<true, false><<<gg, 256>>>(raw, pooler_W, pooler_b, x0,
                                          nullptr, nullptr, 2048, 2048);

    // 3) pool Linear_Block (bias cancels under BN) with fused stats
    gemm_kernel<false, true><<<gg, 256>>>(x0, pool_W, nullptr, y, psum, psq, 1024, 1024);
    bn_scale_kernel<<<4, 256>>>(psum, psq, pool_g, pool_be, scale, shift);
    bn_apply_kernel<<<512, 256>>>(y, scale, shift, p);

    // 4) three towers (emo: nout=7, act: 5, int: 102)
    const int nouts[3] = {7, 5, 102};
    const int offs [3] = {0, 7 * NSEG, 12 * NSEG};
    for (int t = 0; t < 3; ++t) {
        const float* Ws    = (const float*)d_in[9  + 6 * t];
        // d_in[10+6t] = bs: cancelled by BN
        const float* gs    = (const float*)d_in[11 + 6 * t];
        const float* betas = (const float*)d_in[12 + 6 * t];
        const float* Wf    = (const float*)d_in[13 + 6 * t];
        const float* bf    = (const float*)d_in[14 + 6 * t];

        const float* x = p;
        float* pp[2] = {a, b};
        for (int k = 0; k < 4; ++k) {
            gemm_kernel<false, true><<<gg, 256>>>(x, Ws + (size_t)k * DIM * DIM,
                                                  nullptr, y, psum, psq, 1024, 1024);
            float* nx = pp[k & 1];
            bn_scale_kernel<<<4, 256>>>(psum, psq, gs + k * DIM, betas + k * DIM, scale, shift);
            bn_apply_kernel<<<512, 256>>>(y, scale, shift, nx);
            x = nx;
        }
        final_kernel<<<128, 128>>>(x, Wf, bf, out + offs[t], nouts[t]);
    }
}

// round 4
// speedup vs baseline: 3.2216x; 1.9394x over previous
#include <cuda_runtime.h>
#include <cuda_bf16.h>
#include <math_constants.h>
#include <cstdint>
#include <cstddef>

#define DIM 1024
#define NSEG 1024
#define SEQ 2048

// ---------------- static scratch ----------------
// W' tiled bf16: pooler (8 nb * 96 kt) + 13 layers (8 nb * 48 kt), 8192 elems/tile
#define POOLER_WTILES (8 * 96)
#define LAYER_WTILES  (8 * 48)
__device__ __align__(16) __nv_bfloat16 g_Wbf[(POOLER_WTILES + 13 * LAYER_WTILES) * 8192];
__device__ __align__(16) __nv_bfloat16 g_Abf[1024 * 6144];   // pooler input A' (K'=6144)
__device__ __align__(16) __nv_bfloat16 g_Ax [1024 * 3072];   // x0 / tower working A'
__device__ __align__(16) __nv_bfloat16 g_Ap [1024 * 3072];   // pool-block output A'
__device__ __align__(16) float g_y[NSEG * DIM];
__device__ __align__(16) float g_a[NSEG * DIM];

// ---------------- PTX helpers (base sm_90 PTX only; NO tcgen05) ----------------
__device__ __forceinline__ uint32_t smem_u32(const void* p) {
    uint32_t a;
    asm("{ .reg .u64 t; cvta.to.shared.u64 t, %1; cvt.u32.u64 %0, t; }" : "=r"(a) : "l"(p));
    return a;
}
__device__ __forceinline__ void mbar_init(uint32_t a, uint32_t cnt) {
    asm volatile("mbarrier.init.shared.b64 [%0], %1;" :: "r"(a), "r"(cnt) : "memory");
}
__device__ __forceinline__ void mbar_expect_tx(uint32_t a, uint32_t bytes) {
    asm volatile("mbarrier.arrive.expect_tx.shared.b64 _, [%0], %1;" :: "r"(a), "r"(bytes) : "memory");
}
__device__ __forceinline__ void mbar_wait(uint32_t a, uint32_t parity) {
    asm volatile(
        "{\n\t.reg .pred P;\n\t"
        "WL_%=:\n\t"
        "mbarrier.try_wait.parity.acquire.cta.shared::cta.b64 P, [%0], %1, 0x989680;\n\t"
        "@!P bra WL_%=;\n\t}"
        :: "r"(a), "r"(parity) : "memory");
}
__device__ __forceinline__ void mbar_inval(uint32_t a) {
    asm volatile("mbarrier.inval.shared.b64 [%0];" :: "r"(a) : "memory");
}
__device__ __forceinline__ void bulk_g2s(uint32_t dst, const void* src, uint32_t bytes, uint32_t mbar) {
    asm volatile("cp.async.bulk.shared::cta.global.mbarrier::complete_tx::bytes [%0], [%1], %2, [%3];"
                 :: "r"(dst), "l"(src), "r"(bytes), "r"(mbar) : "memory");
}
__device__ __forceinline__ void ldsm4(uint32_t& r0, uint32_t& r1, uint32_t& r2, uint32_t& r3, uint32_t addr) {
    asm volatile("ldmatrix.sync.aligned.m8n8.x4.shared.b16 {%0,%1,%2,%3}, [%4];"
                 : "=r"(r0), "=r"(r1), "=r"(r2), "=r"(r3) : "r"(addr));
}
__device__ __forceinline__ void mma16816(float* c, const uint32_t* a, uint32_t b0, uint32_t b1) {
    asm volatile(
        "mma.sync.aligned.m16n8k16.row.col.f32.bf16.bf16.f32 "
        "{%0,%1,%2,%3}, {%4,%5,%6,%7}, {%8,%9}, {%0,%1,%2,%3};"
        : "+f"(c[0]), "+f"(c[1]), "+f"(c[2]), "+f"(c[3])
        : "r"(a[0]), "r"(a[1]), "r"(a[2]), "r"(a[3]), "r"(b0), "r"(b1));
}

#define SW128(o) ((o) ^ (((o) >> 3) & 0x70))

// hi/lo bf16 split of 8 floats
__device__ __forceinline__ void split8(const float* v, uint4& hi, uint4& lo) {
    __nv_bfloat16* hp = (__nv_bfloat16*)&hi;
    __nv_bfloat16* lp = (__nv_bfloat16*)&lo;
    #pragma unroll
    for (int i = 0; i < 8; ++i) {
        __nv_bfloat16 hb = __float2bfloat16(v[i]);
        hp[i] = hb;
        lp[i] = __float2bfloat16(v[i] - __bfloat162float(hb));
    }
}
// store a 16B group (8 consecutive k' bf16) into tiled+swizzled A'/W' layout
__device__ __forceinline__ void store_tile16(__nv_bfloat16* base, int mb, int nkt,
                                             int trow, int kprime, const uint4& v) {
    int kt = kprime >> 6;
    int tcol = kprime & 63;
    uint32_t off = (uint32_t)trow * 128u + (uint32_t)tcol * 2u;
    off = SW128(off);
    __nv_bfloat16* tile = base + ((size_t)(mb * nkt + kt) << 13);
    *(uint4*)((char*)tile + off) = v;
}

// ---------------- ragged pooling -> A'(pooler) tiles, K'=6144 ----------------
__global__ __launch_bounds__(128)
void pool_kernel(const float* __restrict__ h, const int* __restrict__ turns,
                 const int* __restrict__ parts, __nv_bfloat16* __restrict__ Abf) {
    int s = blockIdx.x;
    int b = s >> 4;
    int j = s & 15;
    int start = 1;
    #pragma unroll
    for (int t = 0; t < 16; ++t)
        if (t < j) start += parts[b * 16 + t];
    int count = parts[b * 16 + j];
    bool valid = (j < turns[b]);
    int c0 = threadIdx.x * 8;
    const float* base = h + ((size_t)b * SEQ + start) * DIM + c0;

    float mx[8], sm[8];
    #pragma unroll
    for (int i = 0; i < 8; ++i) { mx[i] = -CUDART_INF_F; sm[i] = 0.f; }
    if (valid) {
        for (int p = 0; p < count; ++p) {
            float4 v0 = *(const float4*)(base + (size_t)p * DIM);
            float4 v1 = *(const float4*)(base + (size_t)p * DIM + 4);
            float v[8] = {v0.x, v0.y, v0.z, v0.w, v1.x, v1.y, v1.z, v1.w};
            #pragma unroll
            for (int i = 0; i < 8; ++i) { mx[i] = fmaxf(mx[i], v[i]); sm[i] += v[i]; }
        }
        float inv = 1.0f / (float)count;
        #pragma unroll
        for (int i = 0; i < 8; ++i) sm[i] *= inv;
    } else {
        #pragma unroll
        for (int i = 0; i < 8; ++i) sm[i] = CUDART_NAN_F;
    }
    int mb = s >> 7, trow = s & 127;
    uint4 hi, lo;
    split8(mx, hi, lo);
    store_tile16(Abf, mb, 96, trow, c0,        hi);
    store_tile16(Abf, mb, 96, trow, 2048 + c0, hi);
    store_tile16(Abf, mb, 96, trow, 4096 + c0, lo);
    split8(sm, hi, lo);
    store_tile16(Abf, mb, 96, trow, 1024 + c0, hi);
    store_tile16(Abf, mb, 96, trow, 3072 + c0, hi);
    store_tile16(Abf, mb, 96, trow, 5120 + c0, lo);
}

// ---------------- weight conversion: W[K,1024] fp32 -> W' tiled bf16 ----------------
// W' = [Wh, Wl, Wh] along K'; tiles are [128 n-rows x 64 k-cols] SW128 (transposed)
__global__ __launch_bounds__(256)
void wconv_kernel(const float* __restrict__ W, __nv_bfloat16* __restrict__ out,
                  int K, int nkt) {
    __shared__ float sh[64][129];
    int kt = blockIdx.y, nb = blockIdx.x;
    int ksplit = K >> 6;
    int split = kt / ksplit;
    int k0 = (kt - split * ksplit) * 64;
    bool lo = (split == 1);
    int tid = threadIdx.x;
    for (int idx = tid; idx < 2048; idx += 256) {
        int row = idx >> 5, c4 = (idx & 31) * 4;
        float4 v = *(const float4*)&W[(size_t)(k0 + row) * 1024 + nb * 128 + c4];
        sh[row][c4] = v.x; sh[row][c4 + 1] = v.y; sh[row][c4 + 2] = v.z; sh[row][c4 + 3] = v.w;
    }
    __syncthreads();
    int n = tid >> 1, kc0 = (tid & 1) * 32;
    __nv_bfloat16* tile = out + ((size_t)(nb * nkt + kt) << 13);
    #pragma unroll
    for (int g = 0; g < 4; ++g) {
        uint4 o4;
        __nv_bfloat16* o = (__nv_bfloat16*)&o4;
        #pragma unroll
        for (int i = 0; i < 8; ++i) {
            float v = sh[kc0 + g * 8 + i][n];
            __nv_bfloat16 hb = __float2bfloat16(v);
            o[i] = lo ? __float2bfloat16(v - __bfloat162float(hb)) : hb;
        }
        uint32_t off = (uint32_t)n * 128u + (uint32_t)(kc0 + g * 8) * 2u;
        off = SW128(off);
        *(uint4*)((char*)tile + off) = o4;
    }
}

// ---------------- HMMA (mma.sync) bf16 GEMM ----------------
// CTA 128(M) x 64(N); grid (16 nb, 8 mb). 8 warps: 2(m) x 4(n), warp tile 64x16.
// A' tiles [128 m x 64 k] SW128; W' tiles [128 n x 64 k] SW128 (B half-tiles of 64 n).
#define NSTAGE 4
#define STAGE_BYTES 24576
__global__ __launch_bounds__(256)
void mma_gemm(const __nv_bfloat16* __restrict__ Abf, const __nv_bfloat16* __restrict__ Wbf,
              float* __restrict__ Y, int nkt) {
    extern __shared__ char smem[];
    uint32_t base = smem_u32(smem);
    uint32_t tbase = (base + 1023u) & ~1023u;
    uint32_t ctrl = tbase + NSTAGE * STAGE_BYTES;   // mbarriers: 4 x 8B

    int tid = threadIdx.x;
    int wid = tid >> 5, lane = tid & 31;
    int wm = (wid & 1) * 64;
    int wn = (wid >> 1) * 16;

    if (tid == 0) {
        #pragma unroll
        for (int s = 0; s < NSTAGE; ++s) mbar_init(ctrl + s * 8, 1);
    }
    __syncthreads();

    const char* Aptr = (const char*)(Abf + ((size_t)blockIdx.y * nkt << 13));
    const char* Wptr = (const char*)(Wbf + ((size_t)(blockIdx.x >> 1) * nkt << 13));
    uint32_t bhalf = (blockIdx.x & 1) * 8192u;

    if (tid == 0) {
        #pragma unroll
        for (int i = 0; i < NSTAGE; ++i) {
            uint32_t mb = ctrl + i * 8;
            mbar_expect_tx(mb, STAGE_BYTES);
            bulk_g2s(tbase + i * STAGE_BYTES,         Aptr + ((size_t)i << 14), 16384u, mb);
            bulk_g2s(tbase + i * STAGE_BYTES + 16384, Wptr + ((size_t)i << 14) + bhalf, 8192u, mb);
        }
    }

    // per-lane ldmatrix address components
    int rA[4], xA[4];
    #pragma unroll
    for (int i = 0; i < 4; ++i) {
        int row = wm + i * 16 + (lane & 15);
        rA[i] = row * 128;
        xA[i] = (row & 7) << 4;
    }
    int hiA = (lane >> 4) << 4;                          // unit*16 add (0 or 16)
    int rowB = wn + (lane & 7) + ((lane >> 4) << 3);
    int rB = rowB * 128;
    int xB = (rowB & 7) << 4;
    int hiB = ((lane >> 3) & 1) << 4;

    float acc[4][2][4];
    #pragma unroll
    for (int i = 0; i < 4; ++i)
        #pragma unroll
        for (int j = 0; j < 2; ++j)
            #pragma unroll
            for (int q = 0; q < 4; ++q) acc[i][j][q] = 0.f;

    for (int kt = 0; kt < nkt; ++kt) {
        int s = kt & (NSTAGE - 1);
        mbar_wait(ctrl + s * 8, (kt >> 2) & 1);
        uint32_t sA = tbase + s * STAGE_BYTES;
        uint32_t sB = sA + 16384u;
        #pragma unroll
        for (int kk = 0; kk < 4; ++kk) {
            int u = kk << 5;                              // 2*kk*16
            uint32_t b0, b1, b2, b3;
            ldsm4(b0, b1, b2, b3, sB + rB + ((u + hiB) ^ xB));
            #pragma unroll
            for (int i = 0; i < 4; ++i) {
                uint32_t a[4];
                ldsm4(a[0], a[1], a[2], a[3], sA + rA[i] + ((u + hiA) ^ xA[i]));
                mma16816(acc[i][0], a, b0, b1);
                mma16816(acc[i][1], a, b2, b3);
            }
        }
        __syncthreads();
        if (tid == 0 && kt + NSTAGE < nkt) {
            int nk = kt + NSTAGE;
            uint32_t mb = ctrl + s * 8;
            mbar_expect_tx(mb, STAGE_BYTES);
            bulk_g2s(sA, Aptr + ((size_t)nk << 14), 16384u, mb);
            bulk_g2s(sB, Wptr + ((size_t)nk << 14) + bhalf, 8192u, mb);
        }
    }

    // epilogue: fp32 Y
    int r0 = blockIdx.y * 128 + wm + (lane >> 2);
    int cb = blockIdx.x * 64 + wn + ((lane & 3) << 1);
    #pragma unroll
    for (int i = 0; i < 4; ++i) {
        #pragma unroll
        for (int j = 0; j < 2; ++j) {
            int row = r0 + i * 16;
            int col = cb + j * 8;
            *(float2*)&Y[(size_t)row * 1024 + col]       = make_float2(acc[i][j][0], acc[i][j][1]);
            *(float2*)&Y[(size_t)(row + 8) * 1024 + col] = make_float2(acc[i][j][2], acc[i][j][3]);
        }
    }
    __syncthreads();
    if (tid == 0) {
        #pragma unroll
        for (int s = 0; s < NSTAGE; ++s) mbar_inval(ctrl + s * 8);
    }
}

// ---------------- tanh(Y + bias) -> A' tiles (pooler epilogue) ----------------
__global__ __launch_bounds__(256)
void act_kernel(const float* __restrict__ Y, const float* __restrict__ bias,
                __nv_bfloat16* __restrict__ Aout) {
    int c0 = blockIdx.x * 8;
    float bv[8];
    #pragma unroll
    for (int i = 0; i < 8; ++i) bv[i] = bias[c0 + i];
    for (int r = threadIdx.x; r < 1024; r += 256) {
        float4 v0 = *(const float4*)&Y[(size_t)r * 1024 + c0];
        float4 v1 = *(const float4*)&Y[(size_t)r * 1024 + c0 + 4];
        float v[8] = {v0.x, v0.y, v0.z, v0.w, v1.x, v1.y, v1.z, v1.w};
        #pragma unroll
        for (int i = 0; i < 8; ++i) v[i] = tanhf(v[i] + bv[i]);
        uint4 hi, lo;
        split8(v, hi, lo);
        int mb = r >> 7, trow = r & 127;
        store_tile16(Aout, mb, 48, trow, c0,        hi);
        store_tile16(Aout, mb, 48, trow, 1024 + c0, hi);
        store_tile16(Aout, mb, 48, trow, 2048 + c0, lo);
    }
}

// ---------------- BatchNorm(+tanh); writes fp32 + A' tiles ----------------
__global__ __launch_bounds__(256)
void bn_kernel(const float* __restrict__ Y, const float* __restrict__ g,
               const float* __restrict__ beta, float* __restrict__ afp,
               __nv_bfloat16* __restrict__ Abf) {
    __shared__ float ss[32][8], sq[32][8];
    __shared__ float sscale[8], sshift[8];
    int tid = threadIdx.x;
    int c0 = blockIdx.x * 8;
    int c = tid & 7, rg = tid >> 3;
    float s = 0.f, q = 0.f;
    for (int r = rg; r < 1024; r += 32) {
        float v = Y[(size_t)r * 1024 + c0 + c];
        s += v; q += v * v;
    }
    ss[rg][c] = s; sq[rg][c] = q;
    __syncthreads();
    if (tid < 8) {
        float ts = 0.f, tq = 0.f;
        #pragma unroll
        for (int i = 0; i < 32; ++i) { ts += ss[i][tid]; tq += sq[i][tid]; }
        float mean = ts * (1.f / 1024.f);
        float var  = fmaxf(tq * (1.f / 1024.f) - mean * mean, 0.f);
        float rs   = rsqrtf(var + 1e-5f);
        float sc   = g[c0 + tid] * rs;
        sscale[tid] = sc;
        sshift[tid] = beta[c0 + tid] - mean * sc;
    }
    __syncthreads();
    float sc[8], sh[8];
    #pragma unroll
    for (int i = 0; i < 8; ++i) { sc[i] = sscale[i]; sh[i] = sshift[i]; }
    for (int r = tid; r < 1024; r += 256) {
        float4 v0 = *(const float4*)&Y[(size_t)r * 1024 + c0];
        float4 v1 = *(const float4*)&Y[(size_t)r * 1024 + c0 + 4];
        float v[8] = {v0.x, v0.y, v0.z, v0.w, v1.x, v1.y, v1.z, v1.w};
        #pragma unroll
        for (int i = 0; i < 8; ++i) v[i] = tanhf(v[i] * sc[i] + sh[i]);
        *(float4*)&afp[(size_t)r * 1024 + c0]     = make_float4(v[0], v[1], v[2], v[3]);
        *(float4*)&afp[(size_t)r * 1024 + c0 + 4] = make_float4(v[4], v[5], v[6], v[7]);
        uint4 hi, lo;
        split8(v, hi, lo);
        int mb = r >> 7, trow = r & 127;
        store_tile16(Abf, mb, 48, trow, c0,        hi);
        store_tile16(Abf, mb, 48, trow, 1024 + c0, hi);
        store_tile16(Abf, mb, 48, trow, 2048 + c0, lo);
    }
}

// ---------------- small head GEMM ----------------
__global__ __launch_bounds__(128)
void final_kernel(const float* __restrict__ X, const float* __restrict__ Wf,
                  const float* __restrict__ bf, float* __restrict__ out, int nout) {
    __shared__ float sh[8][1024];
    int r0 = blockIdx.x * 8;
    const float4* Xs = (const float4*)(X + (size_t)r0 * 1024);
    #pragma unroll
    for (int q = 0; q < 16; ++q) {
        int i = threadIdx.x + q * 128;
        int row = i >> 8, col4 = (i & 255);
        *(float4*)&sh[row][col4 * 4] = Xs[(size_t)row * 256 + col4];
    }
    __syncthreads();
    for (int n = threadIdx.x; n < nout; n += 128) {
        float acc[8];
        float bv = bf[n];
        #pragma unroll
        for (int r = 0; r < 8; ++r) acc[r] = bv;
        #pragma unroll 8
        for (int k = 0; k < 1024; ++k) {
            float w = Wf[(size_t)k * nout + n];
            #pragma unroll
            for (int r = 0; r < 8; ++r) acc[r] += sh[r][k] * w;
        }
        #pragma unroll
        for (int r = 0; r < 8; ++r)
            out[(size_t)(r0 + r) * nout + n] = acc[r];
    }
}

// ---------------- launch ----------------
#define GEMM_SMEM (NSTAGE * STAGE_BYTES + 1024 + 64)

extern "C" void kernel_launch(void* const* d_in, const int* in_sizes, int n_in,
                              void* d_out, int out_size) {
    const float* h        = (const float*)d_in[0];
    const int*   turns    = (const int*)  d_in[1];
    const int*   parts    = (const int*)  d_in[2];
    const float* pooler_W = (const float*)d_in[3];
    const float* pooler_b = (const float*)d_in[4];
    const float* pool_W   = (const float*)d_in[5];
    // d_in[6] pool_b: cancelled by BN mean subtraction
    const float* pool_g   = (const float*)d_in[7];
    const float* pool_be  = (const float*)d_in[8];
    float* out = (float*)d_out;

    __nv_bfloat16 *Wbf, *Abf, *Ax, *Ap;
    float *y, *a;
    cudaGetSymbolAddress((void**)&Wbf, g_Wbf);
    cudaGetSymbolAddress((void**)&Abf, g_Abf);
    cudaGetSymbolAddress((void**)&Ax,  g_Ax);
    cudaGetSymbolAddress((void**)&Ap,  g_Ap);
    cudaGetSymbolAddress((void**)&y,   g_y);
    cudaGetSymbolAddress((void**)&a,   g_a);

    cudaFuncSetAttribute(mma_gemm, cudaFuncAttributeMaxDynamicSharedMemorySize, GEMM_SMEM);

    // ---- weight conversions ----
    wconv_kernel<<<dim3(8, 96), 256>>>(pooler_W, Wbf, 2048, 96);
    __nv_bfloat16* wl = Wbf + (size_t)POOLER_WTILES * 8192;
    wconv_kernel<<<dim3(8, 48), 256>>>(pool_W, wl, 1024, 48);
    for (int t = 0; t < 3; ++t) {
        const float* Ws = (const float*)d_in[9 + 6 * t];
        for (int k = 0; k < 4; ++k) {
            __nv_bfloat16* dst = wl + (size_t)(1 + t * 4 + k) * LAYER_WTILES * 8192;
            wconv_kernel<<<dim3(8, 48), 256>>>(Ws + (size_t)k * DIM * DIM, dst, 1024, 48);
        }
    }

    // ---- pooling -> A'(pooler) ----
    pool_kernel<<<NSEG, 128>>>(h, turns, parts, Abf);

    // ---- pooler GEMM + tanh(+bias) epilogue -> A'(x0) ----
    mma_gemm<<<dim3(16, 8), 256, GEMM_SMEM>>>(Abf, Wbf, y, 96);
    act_kernel<<<128, 256>>>(y, pooler_b, Ax);

    // ---- pool Linear_Block ----
    mma_gemm<<<dim3(16, 8), 256, GEMM_SMEM>>>(Ax, wl, y, 48);
    bn_kernel<<<128, 256>>>(y, pool_g, pool_be, a, Ap);

    // ---- towers ----
    const int nouts[3] = {7, 5, 102};
    const int offs [3] = {0, 7 * NSEG, 12 * NSEG};
    for (int t = 0; t < 3; ++t) {
        const float* gs    = (const float*)d_in[11 + 6 * t];
        const float* betas = (const float*)d_in[12 + 6 * t];
        const float* Wf    = (const float*)d_in[13 + 6 * t];
        const float* bf    = (const float*)d_in[14 + 6 * t];
        for (int k = 0; k < 4; ++k) {
            const __nv_bfloat16* Ain = (k == 0) ? Ap : Ax;
            __nv_bfloat16* Wl = wl + (size_t)(1 + t * 4 + k) * LAYER_WTILES * 8192;
            mma_gemm<<<dim3(16, 8), 256, GEMM_SMEM>>>(Ain, Wl, y, 48);
            bn_kernel<<<128, 256>>>(y, gs + k * DIM, betas + k * DIM, a, Ax);
        }
        final_kernel<<<128, 128>>>(a, Wf, bf, out + offs[t], nouts[t]);
    }
}